// round 15
// baseline (speedup 1.0000x reference)
#include <cuda_runtime.h>
#include <cuda_bf16.h>

// Problem constants
#define BB 64
#define SS 784
#define TT 500
#define NN 512
#define KS 21
#define TP 522          // output time length
#define THETA 40
#define NT 64           // neurons per tile
#define NTILES 8        // 512/64
#define NTC 6           // time chunks as grid dim (6 * 87 = 522)
#define CH 87           // tau per block
#define SLOTS (CH + KS) // 108 count slots
#define NWARPS 16
#define NMASK 0x0F0F0F0Fu
#define WLCAP 96        // staging capacity (spike count p50 ~39, 9.5 sigma)

// ---- compile-time StepFireLeak response table (verified vs input table in R1) ----
constexpr unsigned coef(int w, int d) {
    int lk = 3 * w - d;
    int leak = lk > 0 ? lk / 2 : 0;
    int st = d + 1;
    return (unsigned)(st < leak ? st : leak);
}
struct CCT { unsigned e[KS]; unsigned o[KS]; };
constexpr CCT make_cc() {
    CCT c{};
    for (int d = 0; d < KS; d++) {
        c.e[d] = coef(0,d) | (coef(2,d) << 8) | (coef(4,d) << 16) | (coef(6,d) << 24);
        c.o[d] = coef(1,d) | (coef(3,d) << 8) | (coef(5,d) << 16) | (coef(7,d) << 24);
    }
    return c;
}
__constant__ CCT G_CC = make_cc();

// Scratch (device globals; statically zero-initialized, no runtime allocation)
__device__ unsigned short g_spk[BB][TT][SS];      // spike lists: PRE-SCALED offsets (s<<6)
__device__ int            g_cnt[BB][TT];          // list lengths (reset by k_main)
__device__ int            g_best[BB][TP][16];     // per-(tile,half) argmax keys
__device__ unsigned char  g_swp[NTILES][SS * NT]; // preprocessed shift bytes [tile][s][n]
__device__ int            g_done[BB];             // per-batch completion counters

// cp.async helpers
#define CP_ASYNC4(dst, src) \
    asm volatile("cp.async.ca.shared.global [%0], [%1], 4;\n" :: "r"(dst), "l"(src))
#define CP_ASYNC16(dst, src) \
    asm volatile("cp.async.cg.shared.global [%0], [%1], 16;\n" :: "r"(dst), "l"(src))
#define CP_COMMIT() asm volatile("cp.async.commit_group;\n" ::: "memory")
#define CP_WAIT1()  asm volatile("cp.async.wait_group 1;\n" ::: "memory")

// ---------------------------------------------------------------------------
// K1: zero output + build spike lists + preprocess weights. grid (SS, BB), 128 thr.
__global__ void k_prep(const float4* __restrict__ x4, const int* __restrict__ weight,
                       float4* __restrict__ out4, int n4) {
    int s = blockIdx.x, b = blockIdx.y;
    int tid = threadIdx.x;
    int g = b * SS + s;

    // zero a slice of out (86 * 50176 >= n4)
    int j = g * 86 + tid;
    if (tid < 86 && j < n4) out4[j] = make_float4(0.f, 0.f, 0.f, 0.f);

    // weight preprocessing (b==0 blocks only): g_swp[tile][s*64+n'] = w<<2
    if (b == 0) {
        for (int n = tid; n < NN; n += 128)
            g_swp[n >> 6][s * NT + (n & 63)] =
                (unsigned char)(weight[(size_t)n * SS + s] << 2);
    }

    // spike lists with PRE-SCALED offsets (s*NT fits u16: 783*64 = 50112)
    unsigned short so = (unsigned short)(s << 6);
    if (tid < TT / 4) {
        float4 v = x4[((size_t)b * SS + s) * (TT / 4) + tid];
        int t = tid * 4;
        if (v.x > 0.5f) { int p = atomicAdd(&g_cnt[b][t + 0], 1); g_spk[b][t + 0][p] = so; }
        if (v.y > 0.5f) { int p = atomicAdd(&g_cnt[b][t + 1], 1); g_spk[b][t + 1][p] = so; }
        if (v.z > 0.5f) { int p = atomicAdd(&g_cnt[b][t + 2], 1); g_spk[b][t + 2][p] = so; }
        if (v.w > 0.5f) { int p = atomicAdd(&g_cnt[b][t + 3], 1); g_spk[b][t + 3][p] = so; }
    }
}

// ---------------------------------------------------------------------------
// K2: potentials + argmax + (last block per batch) depression scan.
// grid = BB*NTILES*NTC = 3072, block = 512.
#define SW_BYTES   (SS * NT)                 // 50176
#define SCNT_OFF   SW_BYTES
#define SCNT_BYTES (SLOTS * NT * 8)          // 55296
#define WL_OFF     (SCNT_OFF + SCNT_BYTES)
#define WL_BYTES   (NWARPS * 2 * WLCAP * 2)  // 6144
#define SCC_OFF    (WL_OFF + WL_BYTES)
#define SCC_BYTES  (SLOTS * 4)               // 432
#define SMEM_BYTES (SCC_OFF + SCC_BYTES)     // 112048

__global__ __launch_bounds__(512, 2) void k_main(float* __restrict__ out) {
    extern __shared__ unsigned char smem[];
    unsigned char* sw = smem;
    unsigned long long* scnt2 = (unsigned long long*)(smem + SCNT_OFF);
    unsigned short* wl = (unsigned short*)(smem + WL_OFF);
    int* scc = (int*)(smem + SCC_OFF);

    int bx = blockIdx.x;
    int b = bx / (NTILES * NTC);
    int r = bx - b * (NTILES * NTC);
    int tile = r / NTC, tc = r - (r / NTC) * NTC;
    int tid = threadIdx.x, lane = tid & 31, warp = tid >> 5;
    int t0 = tc * CH - KS;                     // first t slot (may be <0)

    // sw fill via cp.async (group G0)
    unsigned sw_s = (unsigned)__cvta_generic_to_shared(smem);
    const uint4* src16 = (const uint4*)g_swp[tile];
    for (int k = tid; k < SW_BYTES / 16; k += 512)
        CP_ASYNC16(sw_s + k * 16, src16 + k);
    CP_COMMIT();

    // spike-count cache
    if (tid < SLOTS) {
        int t = t0 + tid;
        scc[tid] = (t >= 0 && t < TT) ? g_cnt[b][t] : 0;
    }

    // first per-warp spike-list prefetch (group G1)
    unsigned short* bufs = wl + warp * 2 * WLCAP;
    unsigned wl_s = (unsigned)__cvta_generic_to_shared(bufs);
    {
        int t = t0 + warp;
        if (t >= 0 && t < TT) {
            int c = g_cnt[b][t];
            int nw = min((c + 1) >> 1, WLCAP / 2);
            const unsigned* src = (const unsigned*)g_spk[b][t];
            for (int k = lane; k < nw; k += 32) CP_ASYNC4(wl_s + k * 4, src + k);
        }
    }
    CP_COMMIT();
    CP_WAIT1();          // G0 (sw) complete for this thread
    __syncthreads();     // all threads' sw copies + scc visible

    const unsigned char* swl = sw + (lane << 1);

    // ---- Phase A: per-slot weight histograms, pipelined staging ----
    int ibuf = 0;
    for (int slot = warp; slot < SLOTS; slot += NWARPS, ibuf ^= 1) {
        int sn = slot + NWARPS;
        if (sn < SLOTS) {
            int tn = t0 + sn;
            if (tn >= 0 && tn < TT) {
                int nw = min((scc[sn] + 1) >> 1, WLCAP / 2);
                const unsigned* src = (const unsigned*)g_spk[b][tn];
                unsigned dst = wl_s + (ibuf ^ 1) * WLCAP * 2;
                for (int k = lane; k < nw; k += 32) CP_ASYNC4(dst + k * 4, src + k);
            }
        }
        CP_COMMIT();
        CP_WAIT1();
        __syncwarp();

        unsigned long long* dst64 = &scnt2[slot * NT];
        int t = t0 + slot;
        if (t < 0 || t >= TT) {
            ((uint4*)dst64)[lane] = make_uint4(0u, 0u, 0u, 0u);
            continue;
        }
        int cnt = scc[slot];
        const unsigned* wlu = (const unsigned*)(bufs + ibuf * WLCAP);
        const unsigned short* wlh = bufs + ibuf * WLCAP;
        unsigned accEa = 0, accOa = 0, accEb = 0, accOb = 0;

        int cmain = min(cnt, WLCAP);
        int k8 = cmain & ~7;
        for (int k = 0; k < k8; k += 8) {
            unsigned p0 = wlu[(k >> 1) + 0], p1 = wlu[(k >> 1) + 1];
            unsigned p2 = wlu[(k >> 1) + 2], p3 = wlu[(k >> 1) + 3];
            unsigned nibA = 0, nibB = 0;
            unsigned w2;
            w2 = *(const unsigned short*)(swl + (p0 & 0xFFFFu));
            nibA += 1u << (w2 & 31u); nibB += 1u << (w2 >> 8);
            w2 = *(const unsigned short*)(swl + (p0 >> 16));
            nibA += 1u << (w2 & 31u); nibB += 1u << (w2 >> 8);
            w2 = *(const unsigned short*)(swl + (p1 & 0xFFFFu));
            nibA += 1u << (w2 & 31u); nibB += 1u << (w2 >> 8);
            w2 = *(const unsigned short*)(swl + (p1 >> 16));
            nibA += 1u << (w2 & 31u); nibB += 1u << (w2 >> 8);
            w2 = *(const unsigned short*)(swl + (p2 & 0xFFFFu));
            nibA += 1u << (w2 & 31u); nibB += 1u << (w2 >> 8);
            w2 = *(const unsigned short*)(swl + (p2 >> 16));
            nibA += 1u << (w2 & 31u); nibB += 1u << (w2 >> 8);
            w2 = *(const unsigned short*)(swl + (p3 & 0xFFFFu));
            nibA += 1u << (w2 & 31u); nibB += 1u << (w2 >> 8);
            w2 = *(const unsigned short*)(swl + (p3 >> 16));
            nibA += 1u << (w2 & 31u); nibB += 1u << (w2 >> 8);
            accEa += nibA & NMASK; accOa += (nibA >> 4) & NMASK;
            accEb += nibB & NMASK; accOb += (nibB >> 4) & NMASK;
        }
        {
            unsigned nibA = 0, nibB = 0;
            for (int k = k8; k < cmain; k++) {
                unsigned w2 = *(const unsigned short*)(swl + (unsigned)wlh[k]);
                nibA += 1u << (w2 & 31u); nibB += 1u << (w2 >> 8);
            }
            accEa += nibA & NMASK; accOa += (nibA >> 4) & NMASK;
            accEb += nibB & NMASK; accOb += (nibB >> 4) & NMASK;
        }
        // cold path: cnt > WLCAP (essentially never at p=0.05)
        for (int j0 = WLCAP; j0 < cnt; j0 += 32) {
            int m = min(32, cnt - j0);
            int sv = (j0 + lane < cnt) ? (int)g_spk[b][t][j0 + lane] : 0;
            unsigned nibA = 0, nibB = 0;
            for (int k = 0; k < m; k++) {
                unsigned so = (unsigned)__shfl_sync(0xffffffffu, sv, k);
                unsigned w2 = *(const unsigned short*)(swl + so);
                nibA += 1u << (w2 & 31u); nibB += 1u << (w2 >> 8);
                if ((k & 7) == 7) {
                    accEa += nibA & NMASK; accOa += (nibA >> 4) & NMASK;
                    accEb += nibB & NMASK; accOb += (nibB >> 4) & NMASK;
                    nibA = nibB = 0;
                }
            }
            accEa += nibA & NMASK; accOa += (nibA >> 4) & NMASK;
            accEb += nibB & NMASK; accOb += (nibB >> 4) & NMASK;
        }
        ((uint4*)dst64)[lane] = make_uint4(accEa, accOa, accEb, accOb);
    }
    __syncthreads();

    // ---- Phase B: 3-tau-shared 21-tap dp4a conv + warp argmax ----
    // Each warp-pair job covers tau = j0, j0+1, j0+2; the 23-slot window union
    // is loaded once, each value feeding up to 3 dp4a pairs (compile-time coeffs).
    {
        int half = warp & 1, pair = warp >> 1;
        int nb = half * 32 + lane;
        int idx16 = tile * 2 + half;
        for (int j0 = pair * 3; j0 < CH; j0 += 24) {    // CH = 87 = 3*29, all covered
            const unsigned long long* base = &scnt2[j0 * NT + nb];
            unsigned pe0 = 0, po0 = 0, pe1 = 0, po1 = 0, pe2 = 0, po2 = 0;
#pragma unroll
            for (int sl = 0; sl < KS + 2; sl++) {       // slots j0+sl, sl in [0,22]
                unsigned long long v = base[sl * NT];
                unsigned vl = (unsigned)v, vh = (unsigned)(v >> 32);
                {   int d = 20 - sl;                    // tau j0+0
                    if (d >= 0) { pe0 = __dp4a(vl, G_CC.e[d], pe0);
                                  po0 = __dp4a(vh, G_CC.o[d], po0); } }
                {   int d = 21 - sl;                    // tau j0+1
                    if (d >= 0 && d < KS) { pe1 = __dp4a(vl, G_CC.e[d], pe1);
                                            po1 = __dp4a(vh, G_CC.o[d], po1); } }
                {   int d = 22 - sl;                    // tau j0+2
                    if (d < KS) { pe2 = __dp4a(vl, G_CC.e[d], pe2);
                                  po2 = __dp4a(vh, G_CC.o[d], po2); } }
            }
            int tau = tc * CH + j0;
            unsigned key0 = ((pe0 + po0) << 12) | ((unsigned)(15 - idx16) << 8) | (255u - lane);
            unsigned key1 = ((pe1 + po1) << 12) | ((unsigned)(15 - idx16) << 8) | (255u - lane);
            unsigned key2 = ((pe2 + po2) << 12) | ((unsigned)(15 - idx16) << 8) | (255u - lane);
            unsigned b0 = __reduce_max_sync(0xffffffffu, key0);
            unsigned b1 = __reduce_max_sync(0xffffffffu, key1);
            unsigned b2 = __reduce_max_sync(0xffffffffu, key2);
            if (lane == 0) {
                g_best[b][tau + 0][idx16] = (int)b0;
                g_best[b][tau + 1][idx16] = (int)b1;
                g_best[b][tau + 2][idx16] = (int)b2;
            }
        }
    }

    // ---- completion: last block of batch b runs the depression scan ----
    __threadfence();
    __syncthreads();
    __shared__ int s_last;
    if (tid == 0)
        s_last = (atomicAdd(&g_done[b], 1) == NTILES * NTC - 1) ? 1 : 0;
    __syncthreads();
    if (s_last) {
        __threadfence();             // acquire: see all blocks' g_best
        int* mk = (int*)scnt2;       // reuse smem
        for (int tau = tid; tau < TP; tau += 512) {
            const int4* p = (const int4*)&g_best[b][tau][0];
            int4 a = p[0], c = p[1], d = p[2], e = p[3];
            int m = max(max(max(a.x, a.y), max(a.z, a.w)),
                        max(max(max(c.x, c.y), max(c.z, c.w)),
                            max(max(max(d.x, d.y), max(d.z, d.w)),
                                max(max(e.x, e.y), max(e.z, e.w)))));
            int pot = (int)((unsigned)m >> 12);
            int neuron = (15 - ((m >> 8) & 15)) * 32 + (255 - (m & 255));
            mk[tau] = (pot << 10) | neuron;
        }
        __syncthreads();
        if (tid == 0) {
            int dep = 0;
            const int4* m4 = (const int4*)mk;
            for (int q = 0; q < 131; q++) {
                int4 v4 = m4[q];
                int vv[4] = {v4.x, v4.y, v4.z, v4.w};
#pragma unroll
                for (int rr = 0; rr < 4; rr++) {
                    int tau = q * 4 + rr;
                    if (tau >= TP) break;
                    int v = vv[rr];
                    if ((v >> 10) > THETA && dep == 0) {
                        out[((size_t)b * NN + (v & 1023)) * TP + tau] = 1.0f;
                        dep = 22;    // becomes 21 after decrement, matching reference
                    }
                    dep = max(0, dep - 1);
                }
            }
        }
        // resets for next call (deterministic across replays)
        for (int t = tid; t < TT; t += 512) g_cnt[b][t] = 0;
        if (tid == 0) g_done[b] = 0;
    }
}

// ---------------------------------------------------------------------------
extern "C" void kernel_launch(void* const* d_in, const int* in_sizes, int n_in,
                              void* d_out, int out_size) {
    const float* x      = (const float*)d_in[0];
    const int*   weight = (const int*)d_in[1];
    float* out = (float*)d_out;

    cudaFuncSetAttribute(k_main, cudaFuncAttributeMaxDynamicSharedMemorySize, SMEM_BYTES);

    int n4 = out_size / 4;
    k_prep<<<dim3(SS, BB), 128>>>((const float4*)x, weight, (float4*)out, n4);
    k_main<<<BB * NTILES * NTC, 512, SMEM_BYTES>>>(out);
}

// round 16
// speedup vs baseline: 1.4125x; 1.4125x over previous
#include <cuda_runtime.h>
#include <cuda_bf16.h>

// Problem constants
#define BB 64
#define SS 784
#define TT 500
#define NN 512
#define KS 21
#define TP 522          // output time length
#define THETA 40
#define NT 64           // neurons per tile
#define NTILES 8        // 512/64
#define NTC 6           // time chunks as grid dim (6 * 87 = 522)
#define CH 87           // tau per block
#define SLOTS (CH + KS) // 108 count slots
#define NWARPS 16
#define NMASK 0x0F0F0F0Fu
#define WLCAP 96        // staging capacity (spike count p50 ~39, 9.5 sigma)
#define SB 8            // synapses per k_prep block
#define PREPB (SS / SB) // 98 blocks in x

// ---- compile-time StepFireLeak response table (verified vs input table in R1) ----
constexpr unsigned coef(int w, int d) {
    int lk = 3 * w - d;
    int leak = lk > 0 ? lk / 2 : 0;
    int st = d + 1;
    return (unsigned)(st < leak ? st : leak);
}
struct CCT { unsigned e[KS]; unsigned o[KS]; };
constexpr CCT make_cc() {
    CCT c{};
    for (int d = 0; d < KS; d++) {
        c.e[d] = coef(0,d) | (coef(2,d) << 8) | (coef(4,d) << 16) | (coef(6,d) << 24);
        c.o[d] = coef(1,d) | (coef(3,d) << 8) | (coef(5,d) << 16) | (coef(7,d) << 24);
    }
    return c;
}
__constant__ CCT G_CC = make_cc();

// Scratch (device globals; statically zero-initialized, no runtime allocation)
__device__ unsigned short g_spk[BB][TT][SS];      // spike lists (raw s indices)
__device__ int            g_cnt[BB][TT];          // list lengths (reset by k_main)
__device__ int            g_best[BB][TP][16];     // per-(tile,half) argmax keys
__device__ unsigned char  g_swp[NTILES][SS * NT]; // preprocessed shift bytes [tile][s][n]
__device__ int            g_done[BB];             // per-batch completion counters

// cp.async helpers
#define CP_ASYNC4(dst, src) \
    asm volatile("cp.async.ca.shared.global [%0], [%1], 4;\n" :: "r"(dst), "l"(src))
#define CP_ASYNC16(dst, src) \
    asm volatile("cp.async.cg.shared.global [%0], [%1], 16;\n" :: "r"(dst), "l"(src))
#define CP_COMMIT() asm volatile("cp.async.commit_group;\n" ::: "memory")
#define CP_WAIT1()  asm volatile("cp.async.wait_group 1;\n" ::: "memory")

// ---------------------------------------------------------------------------
// K1: zero output + build spike lists + preprocess weights.
// grid (98, 64), 512 threads; each block covers 8 synapses of one batch.
__global__ __launch_bounds__(512) void k_prep(const float4* __restrict__ x4,
                                              const int* __restrict__ weight,
                                              float4* __restrict__ out4, int n4) {
    int bs = blockIdx.x, b = blockIdx.y;
    int tid = threadIdx.x;
    int s0 = bs * SB;

    // zero out[] via grid-stride over all 6272*512 threads
    for (int j = (b * PREPB + bs) * 512 + tid; j < n4; j += PREPB * BB * 512)
        out4[j] = make_float4(0.f, 0.f, 0.f, 0.f);

    // weight preprocessing (b==0 plane only): g_swp[tile][s*64+n'] = w<<2
    if (b == 0) {
        for (int i = tid; i < SB * NN; i += 512) {
            int sl = i >> 9, n = i & 511;
            int s = s0 + sl;
            g_swp[n >> 6][s * NT + (n & 63)] =
                (unsigned char)(weight[(size_t)n * SS + s] << 2);
        }
    }

    // spike lists: 8 s x 125 float4 reads
    for (int i = tid; i < SB * (TT / 4); i += 512) {
        int sl = i / (TT / 4), t4 = i - sl * (TT / 4);
        int s = s0 + sl;
        float4 v = x4[((size_t)b * SS + s) * (TT / 4) + t4];
        int t = t4 * 4;
        unsigned short sv = (unsigned short)s;
        if (v.x > 0.5f) { int p = atomicAdd(&g_cnt[b][t + 0], 1); g_spk[b][t + 0][p] = sv; }
        if (v.y > 0.5f) { int p = atomicAdd(&g_cnt[b][t + 1], 1); g_spk[b][t + 1][p] = sv; }
        if (v.z > 0.5f) { int p = atomicAdd(&g_cnt[b][t + 2], 1); g_spk[b][t + 2][p] = sv; }
        if (v.w > 0.5f) { int p = atomicAdd(&g_cnt[b][t + 3], 1); g_spk[b][t + 3][p] = sv; }
    }
}

// ---------------------------------------------------------------------------
// K2: potentials + argmax + (last block per batch) depression scan.
// grid = BB*NTILES*NTC = 3072, block = 512.  (verbatim R12 k_main)
#define SW_BYTES   (SS * NT)                 // 50176
#define SCNT_OFF   SW_BYTES
#define SCNT_BYTES (SLOTS * NT * 8)          // 55296
#define WL_OFF     (SCNT_OFF + SCNT_BYTES)
#define WL_BYTES   (NWARPS * 2 * WLCAP * 2)  // 6144
#define SCC_OFF    (WL_OFF + WL_BYTES)
#define SCC_BYTES  (SLOTS * 4)               // 432
#define SMEM_BYTES (SCC_OFF + SCC_BYTES)     // 112048

__global__ __launch_bounds__(512, 2) void k_main(float* __restrict__ out) {
    extern __shared__ unsigned char smem[];
    unsigned char* sw = smem;
    unsigned long long* scnt2 = (unsigned long long*)(smem + SCNT_OFF);
    unsigned short* wl = (unsigned short*)(smem + WL_OFF);
    int* scc = (int*)(smem + SCC_OFF);

    int bx = blockIdx.x;
    int b = bx / (NTILES * NTC);
    int r = bx - b * (NTILES * NTC);
    int tile = r / NTC, tc = r - (r / NTC) * NTC;
    int tid = threadIdx.x, lane = tid & 31, warp = tid >> 5;
    int t0 = tc * CH - KS;                     // first t slot (may be <0)

    // sw fill via cp.async (group G0)
    unsigned sw_s = (unsigned)__cvta_generic_to_shared(smem);
    const uint4* src16 = (const uint4*)g_swp[tile];
    for (int k = tid; k < SW_BYTES / 16; k += 512)
        CP_ASYNC16(sw_s + k * 16, src16 + k);
    CP_COMMIT();

    // spike-count cache
    if (tid < SLOTS) {
        int t = t0 + tid;
        scc[tid] = (t >= 0 && t < TT) ? g_cnt[b][t] : 0;
    }

    // first per-warp spike-list prefetch (group G1)
    unsigned short* bufs = wl + warp * 2 * WLCAP;
    unsigned wl_s = (unsigned)__cvta_generic_to_shared(bufs);
    {
        int t = t0 + warp;
        if (t >= 0 && t < TT) {
            int c = g_cnt[b][t];
            int nw = min((c + 1) >> 1, WLCAP / 2);
            const unsigned* src = (const unsigned*)g_spk[b][t];
            for (int k = lane; k < nw; k += 32) CP_ASYNC4(wl_s + k * 4, src + k);
        }
    }
    CP_COMMIT();
    CP_WAIT1();          // G0 (sw) complete for this thread
    __syncthreads();     // all threads' sw copies + scc visible

    const unsigned char* swl = sw + (lane << 1);

    // ---- Phase A: per-slot weight histograms, pipelined staging ----
    int ibuf = 0;
    for (int slot = warp; slot < SLOTS; slot += NWARPS, ibuf ^= 1) {
        int sn = slot + NWARPS;
        if (sn < SLOTS) {
            int tn = t0 + sn;
            if (tn >= 0 && tn < TT) {
                int nw = min((scc[sn] + 1) >> 1, WLCAP / 2);
                const unsigned* src = (const unsigned*)g_spk[b][tn];
                unsigned dst = wl_s + (ibuf ^ 1) * WLCAP * 2;
                for (int k = lane; k < nw; k += 32) CP_ASYNC4(dst + k * 4, src + k);
            }
        }
        CP_COMMIT();
        CP_WAIT1();
        __syncwarp();

        unsigned long long* dst64 = &scnt2[slot * NT];
        int t = t0 + slot;
        if (t < 0 || t >= TT) {
            ((uint4*)dst64)[lane] = make_uint4(0u, 0u, 0u, 0u);
            continue;
        }
        int cnt = scc[slot];
        const unsigned* wlu = (const unsigned*)(bufs + ibuf * WLCAP);
        const unsigned short* wlh = bufs + ibuf * WLCAP;
        unsigned accEa = 0, accOa = 0, accEb = 0, accOb = 0;

        int cmain = min(cnt, WLCAP);
        int k8 = cmain & ~7;
        for (int k = 0; k < k8; k += 8) {
            unsigned p0 = wlu[(k >> 1) + 0], p1 = wlu[(k >> 1) + 1];
            unsigned p2 = wlu[(k >> 1) + 2], p3 = wlu[(k >> 1) + 3];
            unsigned nibA = 0, nibB = 0;
            unsigned w2;
            w2 = *(const unsigned short*)(swl + ((p0 & 0xFFFFu) * NT));
            nibA += 1u << (w2 & 31u); nibB += 1u << (w2 >> 8);
            w2 = *(const unsigned short*)(swl + ((p0 >> 16) * NT));
            nibA += 1u << (w2 & 31u); nibB += 1u << (w2 >> 8);
            w2 = *(const unsigned short*)(swl + ((p1 & 0xFFFFu) * NT));
            nibA += 1u << (w2 & 31u); nibB += 1u << (w2 >> 8);
            w2 = *(const unsigned short*)(swl + ((p1 >> 16) * NT));
            nibA += 1u << (w2 & 31u); nibB += 1u << (w2 >> 8);
            w2 = *(const unsigned short*)(swl + ((p2 & 0xFFFFu) * NT));
            nibA += 1u << (w2 & 31u); nibB += 1u << (w2 >> 8);
            w2 = *(const unsigned short*)(swl + ((p2 >> 16) * NT));
            nibA += 1u << (w2 & 31u); nibB += 1u << (w2 >> 8);
            w2 = *(const unsigned short*)(swl + ((p3 & 0xFFFFu) * NT));
            nibA += 1u << (w2 & 31u); nibB += 1u << (w2 >> 8);
            w2 = *(const unsigned short*)(swl + ((p3 >> 16) * NT));
            nibA += 1u << (w2 & 31u); nibB += 1u << (w2 >> 8);
            accEa += nibA & NMASK; accOa += (nibA >> 4) & NMASK;
            accEb += nibB & NMASK; accOb += (nibB >> 4) & NMASK;
        }
        {
            unsigned nibA = 0, nibB = 0;
            for (int k = k8; k < cmain; k++) {
                unsigned w2 = *(const unsigned short*)(swl + ((unsigned)wlh[k] * NT));
                nibA += 1u << (w2 & 31u); nibB += 1u << (w2 >> 8);
            }
            accEa += nibA & NMASK; accOa += (nibA >> 4) & NMASK;
            accEb += nibB & NMASK; accOb += (nibB >> 4) & NMASK;
        }
        // cold path: cnt > WLCAP (essentially never at p=0.05)
        for (int j0 = WLCAP; j0 < cnt; j0 += 32) {
            int m = min(32, cnt - j0);
            int sv = (j0 + lane < cnt) ? (int)g_spk[b][t][j0 + lane] : 0;
            unsigned nibA = 0, nibB = 0;
            for (int k = 0; k < m; k++) {
                int s = __shfl_sync(0xffffffffu, sv, k);
                unsigned w2 = *(const unsigned short*)(swl + (unsigned)s * NT);
                nibA += 1u << (w2 & 31u); nibB += 1u << (w2 >> 8);
                if ((k & 7) == 7) {
                    accEa += nibA & NMASK; accOa += (nibA >> 4) & NMASK;
                    accEb += nibB & NMASK; accOb += (nibB >> 4) & NMASK;
                    nibA = nibB = 0;
                }
            }
            accEa += nibA & NMASK; accOa += (nibA >> 4) & NMASK;
            accEb += nibB & NMASK; accOb += (nibB >> 4) & NMASK;
        }
        ((uint4*)dst64)[lane] = make_uint4(accEa, accOa, accEb, accOb);
    }
    __syncthreads();

    // ---- Phase B: 21-tap dp4a conv (constant-bank coeffs) + warp argmax ----
    {
        int half = warp & 1, pair = warp >> 1;
        int nb = half * 32 + lane;
        int idx16 = tile * 2 + half;
        for (int j = pair; j < CH; j += 8) {
            int tau = tc * CH + j;
            const unsigned long long* p0 = &scnt2[j * NT + nb];
            unsigned pe0 = 0, pe1 = 0, po0 = 0, po1 = 0;
#pragma unroll
            for (int d = 0; d < KS; d++) {
                unsigned long long v = p0[(20 - d) * NT];
                if (d & 1) { pe1 = __dp4a((unsigned)v, G_CC.e[d], pe1);
                             po1 = __dp4a((unsigned)(v >> 32), G_CC.o[d], po1); }
                else       { pe0 = __dp4a((unsigned)v, G_CC.e[d], pe0);
                             po0 = __dp4a((unsigned)(v >> 32), G_CC.o[d], po0); }
            }
            unsigned pot = (pe0 + pe1) + (po0 + po1);
            unsigned key = (pot << 12) | ((unsigned)(15 - idx16) << 8) | (255u - lane);
            unsigned best = __reduce_max_sync(0xffffffffu, key);
            if (lane == 0) g_best[b][tau][idx16] = (int)best;
        }
    }

    // ---- completion: last block of batch b runs the depression scan ----
    __threadfence();
    __syncthreads();
    __shared__ int s_last;
    if (tid == 0)
        s_last = (atomicAdd(&g_done[b], 1) == NTILES * NTC - 1) ? 1 : 0;
    __syncthreads();
    if (s_last) {
        __threadfence();             // acquire: see all blocks' g_best
        int* mk = (int*)scnt2;       // reuse smem
        for (int tau = tid; tau < TP; tau += 512) {
            const int4* p = (const int4*)&g_best[b][tau][0];
            int4 a = p[0], c = p[1], d = p[2], e = p[3];
            int m = max(max(max(a.x, a.y), max(a.z, a.w)),
                        max(max(max(c.x, c.y), max(c.z, c.w)),
                            max(max(max(d.x, d.y), max(d.z, d.w)),
                                max(max(e.x, e.y), max(e.z, e.w)))));
            int pot = (int)((unsigned)m >> 12);
            int neuron = (15 - ((m >> 8) & 15)) * 32 + (255 - (m & 255));
            mk[tau] = (pot << 10) | neuron;
        }
        __syncthreads();
        if (tid == 0) {
            int dep = 0;
            const int4* m4 = (const int4*)mk;
            for (int q = 0; q < 131; q++) {
                int4 v4 = m4[q];
                int vv[4] = {v4.x, v4.y, v4.z, v4.w};
#pragma unroll
                for (int rr = 0; rr < 4; rr++) {
                    int tau = q * 4 + rr;
                    if (tau >= TP) break;
                    int v = vv[rr];
                    if ((v >> 10) > THETA && dep == 0) {
                        out[((size_t)b * NN + (v & 1023)) * TP + tau] = 1.0f;
                        dep = 22;    // becomes 21 after decrement, matching reference
                    }
                    dep = max(0, dep - 1);
                }
            }
        }
        // resets for next call (deterministic across replays)
        for (int t = tid; t < TT; t += 512) g_cnt[b][t] = 0;
        if (tid == 0) g_done[b] = 0;
    }
}

// ---------------------------------------------------------------------------
extern "C" void kernel_launch(void* const* d_in, const int* in_sizes, int n_in,
                              void* d_out, int out_size) {
    const float* x      = (const float*)d_in[0];
    const int*   weight = (const int*)d_in[1];
    float* out = (float*)d_out;

    cudaFuncSetAttribute(k_main, cudaFuncAttributeMaxDynamicSharedMemorySize, SMEM_BYTES);

    int n4 = out_size / 4;
    k_prep<<<dim3(PREPB, BB), 512>>>((const float4*)x, weight, (float4*)out, n4);
    k_main<<<BB * NTILES * NTC, 512, SMEM_BYTES>>>(out);
}